// round 5
// baseline (speedup 1.0000x reference)
#include <cuda_runtime.h>
#include <cuda_bf16.h>

// TopKPool_16372415332892
// out[b] = (1/K) * sum_{topK rows} x[row] * tanh((x[row].w)/||w||)
// B=256, N=512, D=256, K=256. edge_index/batch dead.

#define BB 256
#define NN 512
#define DD 256
#define KK 256

__device__ int   g_idx[BB * KK];           // selected node idx (compacted by rank)
__device__ float g_gate[BB * KK];          // tanh-gated scores
__device__ float g_part[BB * 4 * DD];      // gather partials (4 chunks/graph)

// ---------- Kernel 1: fused score + rank (block per graph, 1024 thr) ----------
__global__ __launch_bounds__(1024, 2)
void score_rank_kernel(const float* __restrict__ x, const float* __restrict__ w)
{
    __shared__ float sh_score[NN];
    __shared__ int   sh_cnt[2 * NN];
    __shared__ float sh_red[8];
    __shared__ float sh_inv;

    const int tid  = threadIdx.x;
    const int lane = tid & 31;
    const int warp = tid >> 5;
    const int b    = blockIdx.x;

    // ||w||^-1 via warp 0
    if (warp == 0) {
        float ssq = 0.f;
        #pragma unroll
        for (int i = 0; i < 8; i++) { float v = w[lane + i * 32]; ssq += v * v; }
        #pragma unroll
        for (int o = 16; o; o >>= 1) ssq += __shfl_xor_sync(0xffffffffu, ssq, o);
        if (lane == 0) sh_inv = rsqrtf(ssq);
    }

    // weight fragment in registers
    const float4 wa = *reinterpret_cast<const float4*>(w + lane * 4);
    const float4 wb = *reinterpret_cast<const float4*>(w + 128 + lane * 4);

    const float* xb = x + (size_t)b * NN * DD;

    // scores: warp w handles rows [w*16, w*16+16); 32 warps cover 512 rows
    #pragma unroll 4
    for (int r = warp * 16; r < warp * 16 + 16; r++) {
        const float* row = xb + (size_t)r * DD;
        const float4 xa = *reinterpret_cast<const float4*>(row + lane * 4);
        const float4 xc = *reinterpret_cast<const float4*>(row + 128 + lane * 4);
        float d = xa.x * wa.x + xa.y * wa.y + xa.z * wa.z + xa.w * wa.w
                + xc.x * wb.x + xc.y * wb.y + xc.z * wb.z + xc.w * wb.w;
        #pragma unroll
        for (int o = 16; o; o >>= 1) d += __shfl_xor_sync(0xffffffffu, d, o);
        if (lane == 0) sh_score[r] = d;
    }
    __syncthreads();

    // rank: thread (i = tid&511, h = tid>>9) counts half of the comparisons
    {
        const int i  = tid & (NN - 1);
        const int h  = tid >> 9;
        const int j0 = h * (NN / 2);
        const float si = sh_score[i];
        int cnt = 0;
        #pragma unroll 8
        for (int j = j0; j < j0 + NN / 2; j++) {
            const float sj = sh_score[j];
            cnt += (sj > si) || (sj == si && j < i);
        }
        sh_cnt[h * NN + i] = cnt;
    }
    __syncthreads();

    // combine halves; rank unique -> free compaction
    if (tid < NN) {
        const int cnt = sh_cnt[tid] + sh_cnt[NN + tid];
        if (cnt < KK) {
            g_idx[b * KK + cnt]  = tid;
            g_gate[b * KK + cnt] = tanhf(sh_score[tid] * sh_inv);
        }
    }
}

// ---------- Kernel 2: gather (4 blocks per graph, 64 rows each) ----------
__global__ __launch_bounds__(256)
void gather_kernel(const float* __restrict__ x)
{
    __shared__ int   sidx[64];
    __shared__ float sgate[64];

    const int tid = threadIdx.x;
    const int b   = blockIdx.x >> 2;
    const int c   = blockIdx.x & 3;

    if (tid < 64) {
        sidx[tid]  = g_idx[b * KK + c * 64 + tid];
        sgate[tid] = g_gate[b * KK + c * 64 + tid];
    }
    __syncthreads();

    const float* xb = x + (size_t)b * NN * DD;
    float acc = 0.f;
    #pragma unroll 16
    for (int k = 0; k < 64; k++) {
        acc += xb[(size_t)sidx[k] * DD + tid] * sgate[k];
    }
    g_part[blockIdx.x * DD + tid] = acc;
}

// ---------- Kernel 3: reduce partials ----------
__global__ __launch_bounds__(256)
void reduce_kernel(float* __restrict__ out)
{
    const int b = blockIdx.x;
    const int t = threadIdx.x;
    const float* p = g_part + b * 4 * DD;
    out[b * DD + t] = (p[t] + p[DD + t] + p[2 * DD + t] + p[3 * DD + t])
                      * (1.0f / (float)KK);
}

extern "C" void kernel_launch(void* const* d_in, const int* in_sizes, int n_in,
                              void* d_out, int out_size)
{
    (void)in_sizes; (void)n_in; (void)out_size;
    const float* x = (const float*)d_in[0];
    const float* w = (const float*)d_in[1];
    float* out = (float*)d_out;

    score_rank_kernel<<<BB, 1024>>>(x, w);
    gather_kernel<<<BB * 4, 256>>>(x);
    reduce_kernel<<<BB, 256>>>(out);
}

// round 8
// speedup vs baseline: 1.2058x; 1.2058x over previous
#include <cuda_runtime.h>
#include <cuda_bf16.h>

// TopKPool_16372415332892
// out[b] = (1/K) * sum_{topK rows} x[row] * tanh((x[row].w)/||w||)
// B=256, N=512, D=256, K=256. edge_index/batch dead inputs.

#define BB 256
#define NN 512
#define DD 256
#define KK 256

__device__ float g_score[BB * NN];   // raw dot products (selection monotone in this)
__device__ int2  g_sel[BB * KK];     // {node idx, gate as float bits}, compacted

// ---------------- Kernel 1: scores (warp per row, wide grid) ----------------
// grid = B*N/8 = 16384 blocks, 256 threads (8 warps -> 8 rows/block).
__global__ __launch_bounds__(256)
void score_kernel(const float* __restrict__ x, const float* __restrict__ w)
{
    const int lane = threadIdx.x & 31;
    const int warp = threadIdx.x >> 5;
    const int row  = blockIdx.x * 8 + warp;

    const float4 wa = *reinterpret_cast<const float4*>(w + lane * 4);
    const float4 wb = *reinterpret_cast<const float4*>(w + 128 + lane * 4);

    const float* r = x + (size_t)row * DD;
    const float4 xa = *reinterpret_cast<const float4*>(r + lane * 4);
    const float4 xc = *reinterpret_cast<const float4*>(r + 128 + lane * 4);

    float d = xa.x * wa.x + xa.y * wa.y + xa.z * wa.z + xa.w * wa.w
            + xc.x * wb.x + xc.y * wb.y + xc.z * wb.z + xc.w * wb.w;
    #pragma unroll
    for (int o = 16; o; o >>= 1) d += __shfl_xor_sync(0xffffffffu, d, o);
    if (lane == 0) g_score[row] = d;
}

// ---------------- Kernel 2: radix top-K select (block per graph) ----------------
// 512 threads; thread tid owns node tid. 4 passes of 8-bit histogram radix-select
// over the ordered-uint mapping of the score, then exact lower-index tie-break.
__global__ __launch_bounds__(512)
void rank_kernel(const float* __restrict__ w)
{
    __shared__ unsigned hist[256];
    __shared__ unsigned sscan[256];   // sscan[v] = # active nodes with byte >= v
    __shared__ unsigned s_t, s_gt, s_remk;
    __shared__ int s_wcnt[16];
    __shared__ float s_inv;

    const int tid  = threadIdx.x;
    const int lane = tid & 31;
    const int warp = tid >> 5;
    const int b    = blockIdx.x;

    // ||w||^-1 (warp 0)
    if (warp == 0) {
        float ssq = 0.f;
        #pragma unroll
        for (int i = 0; i < 8; i++) { float v = w[lane + i * 32]; ssq += v * v; }
        #pragma unroll
        for (int o = 16; o; o >>= 1) ssq += __shfl_xor_sync(0xffffffffu, ssq, o);
        if (lane == 0) s_inv = rsqrtf(ssq);
    }
    if (tid == 0) s_remk = KK;

    const float s = g_score[b * NN + tid];
    const unsigned bits = __float_as_uint(s);
    const unsigned key  = (bits & 0x80000000u) ? ~bits : (bits | 0x80000000u);

    bool active = true, selected = false;

    #pragma unroll
    for (int pass = 0; pass < 4; ++pass) {
        if (tid < 256) hist[tid] = 0u;
        __syncthreads();
        const unsigned byt = (key >> (24 - 8 * pass)) & 0xFFu;
        if (active) atomicAdd(&hist[byt], 1u);
        __syncthreads();

        // suffix scan of hist by warp 0: lane l owns bins [8l, 8l+8)
        if (warp == 0) {
            unsigned tot = 0;
            #pragma unroll
            for (int j = 0; j < 8; j++) tot += hist[lane * 8 + j];
            unsigned suf = tot;  // inclusive suffix over lane segment sums
            #pragma unroll
            for (int o = 1; o < 32; o <<= 1) {
                unsigned t2 = __shfl_down_sync(0xffffffffu, suf, o);
                if (lane + o < 32) suf += t2;
            }
            unsigned run = suf - tot;          // count with byte >= 8(l+1)
            #pragma unroll
            for (int j = 7; j >= 0; --j) {
                run += hist[lane * 8 + j];
                sscan[lane * 8 + j] = run;     // count with byte >= 8l+j
            }
        }
        __syncthreads();

        const unsigned remk = s_remk;
        if (tid < 256) {
            const unsigned ge = sscan[tid];
            const unsigned gt = (tid == 255) ? 0u : sscan[tid + 1];
            if (ge >= remk && gt < remk) { s_t = (unsigned)tid; s_gt = gt; }
        }
        __syncthreads();

        const unsigned t = s_t;
        if (active) {
            if (byt > t)      { selected = true; active = false; }
            else if (byt < t) { active = false; }
        }
        if (tid == 0) s_remk = remk - s_gt;
        __syncthreads();
    }

    // Remaining actives have score bitwise-equal to the K-th threshold:
    // select the s_remk smallest indices (jax.lax.top_k tie-break).
    {
        const unsigned m_act = __ballot_sync(0xffffffffu, active);
        if (lane == 0) s_wcnt[warp] = __popc(m_act);
        __syncthreads();
        if (tid == 0) {
            int run = 0;
            #pragma unroll
            for (int i = 0; i < 16; i++) { int c = s_wcnt[i]; s_wcnt[i] = run; run += c; }
        }
        __syncthreads();
        if (active) {
            const int irank = s_wcnt[warp] + __popc(m_act & ((1u << lane) - 1u));
            if ((unsigned)irank < s_remk) selected = true;
        }
        __syncthreads();
    }

    // Deterministic compaction of the K selected nodes.
    const unsigned m_sel = __ballot_sync(0xffffffffu, selected);
    if (lane == 0) s_wcnt[warp] = __popc(m_sel);
    __syncthreads();
    if (tid == 0) {
        int run = 0;
        #pragma unroll
        for (int i = 0; i < 16; i++) { int c = s_wcnt[i]; s_wcnt[i] = run; run += c; }
    }
    __syncthreads();
    if (selected) {
        const int slot = s_wcnt[warp] + __popc(m_sel & ((1u << lane) - 1u));
        g_sel[b * KK + slot] = make_int2(tid, __float_as_int(tanhf(s * s_inv)));
    }
}

// ---------------- Kernel 3: gather, direct write (block = graph x col-half) ----------------
__global__ __launch_bounds__(128)
void gather_kernel(const float* __restrict__ x, float* __restrict__ out)
{
    __shared__ int2 s_sel[KK];

    const int tid = threadIdx.x;
    const int b   = blockIdx.x >> 1;
    const int h   = blockIdx.x & 1;

    s_sel[tid]       = g_sel[b * KK + tid];
    s_sel[tid + 128] = g_sel[b * KK + tid + 128];
    __syncthreads();

    const float* xb = x + (size_t)b * NN * DD + h * 128 + tid;
    float acc = 0.f;
    #pragma unroll 8
    for (int k = 0; k < KK; k++) {
        const int2 p = s_sel[k];
        acc += xb[(size_t)p.x * DD] * __int_as_float(p.y);
    }
    out[b * DD + h * 128 + tid] = acc * (1.0f / (float)KK);
}

extern "C" void kernel_launch(void* const* d_in, const int* in_sizes, int n_in,
                              void* d_out, int out_size)
{
    (void)in_sizes; (void)n_in; (void)out_size;
    const float* x = (const float*)d_in[0];
    const float* w = (const float*)d_in[1];
    float* out = (float*)d_out;

    score_kernel<<<(BB * NN) / 8, 256>>>(x, w);
    rank_kernel<<<BB, 512>>>(w);
    gather_kernel<<<BB * 2, 128>>>(x, out);
}

// round 9
// speedup vs baseline: 1.5338x; 1.2720x over previous
#include <cuda_runtime.h>
#include <cuda_bf16.h>

// TopKPool_16372415332892
// out[b] = (1/K) * sum_{topK rows} x[row] * tanh((x[row].w)/||w||)
// B=256, N=512, D=256, K=256. edge_index/batch dead inputs.

#define BB 256
#define NN 512
#define DD 256
#define KK 256

__device__ float g_score[BB * NN];     // raw dot products (selection monotone in this)
__device__ int2  g_sel[BB * KK];       // {node idx, gate bits}, compacted by rank
__device__ float g_part[BB * 4 * DD];  // gather partials (4 chunks/graph)

// ---------------- Kernel 1: scores (2 rows per warp -> 4 indep LDG.128/thread) ----------------
// grid = B*N/16 = 8192 blocks, 256 threads (8 warps x 2 rows = 16 rows/block).
__global__ __launch_bounds__(256)
void score_kernel(const float* __restrict__ x, const float* __restrict__ w)
{
    const int lane = threadIdx.x & 31;
    const int warp = threadIdx.x >> 5;
    const int row0 = blockIdx.x * 16 + warp * 2;

    const float4 wa = *reinterpret_cast<const float4*>(w + lane * 4);
    const float4 wb = *reinterpret_cast<const float4*>(w + 128 + lane * 4);

    const float* r0 = x + (size_t)row0 * DD;
    const float* r1 = r0 + DD;
    const float4 a0 = *reinterpret_cast<const float4*>(r0 + lane * 4);
    const float4 c0 = *reinterpret_cast<const float4*>(r0 + 128 + lane * 4);
    const float4 a1 = *reinterpret_cast<const float4*>(r1 + lane * 4);
    const float4 c1 = *reinterpret_cast<const float4*>(r1 + 128 + lane * 4);

    float d0 = a0.x * wa.x + a0.y * wa.y + a0.z * wa.z + a0.w * wa.w
             + c0.x * wb.x + c0.y * wb.y + c0.z * wb.z + c0.w * wb.w;
    float d1 = a1.x * wa.x + a1.y * wa.y + a1.z * wa.z + a1.w * wa.w
             + c1.x * wb.x + c1.y * wb.y + c1.z * wb.z + c1.w * wb.w;
    #pragma unroll
    for (int o = 16; o; o >>= 1) {
        d0 += __shfl_xor_sync(0xffffffffu, d0, o);
        d1 += __shfl_xor_sync(0xffffffffu, d1, o);
    }
    if (lane == 0) {
        g_score[row0]     = d0;
        g_score[row0 + 1] = d1;
    }
}

// ---------------- Kernel 2: radix top-K select (block per graph, 512 thr) ----------------
__global__ __launch_bounds__(512)
void rank_kernel(const float* __restrict__ w)
{
    __shared__ unsigned hist[256];
    __shared__ unsigned sscan[256];   // sscan[v] = # active nodes with byte >= v
    __shared__ unsigned s_t, s_gt, s_remk;
    __shared__ int s_wcnt[16];
    __shared__ float s_inv;

    const int tid  = threadIdx.x;
    const int lane = tid & 31;
    const int warp = tid >> 5;
    const int b    = blockIdx.x;

    if (warp == 0) {
        float ssq = 0.f;
        #pragma unroll
        for (int i = 0; i < 8; i++) { float v = w[lane + i * 32]; ssq += v * v; }
        #pragma unroll
        for (int o = 16; o; o >>= 1) ssq += __shfl_xor_sync(0xffffffffu, ssq, o);
        if (lane == 0) s_inv = rsqrtf(ssq);
    }
    if (tid == 0) s_remk = KK;

    const float s = g_score[b * NN + tid];
    const unsigned bits = __float_as_uint(s);
    const unsigned key  = (bits & 0x80000000u) ? ~bits : (bits | 0x80000000u);

    bool active = true, selected = false;

    #pragma unroll
    for (int pass = 0; pass < 4; ++pass) {
        if (tid < 256) hist[tid] = 0u;
        __syncthreads();
        const unsigned byt = (key >> (24 - 8 * pass)) & 0xFFu;
        if (active) atomicAdd(&hist[byt], 1u);
        __syncthreads();

        // suffix scan of hist by warp 0: lane l owns bins [8l, 8l+8)
        if (warp == 0) {
            unsigned tot = 0;
            #pragma unroll
            for (int j = 0; j < 8; j++) tot += hist[lane * 8 + j];
            unsigned suf = tot;
            #pragma unroll
            for (int o = 1; o < 32; o <<= 1) {
                unsigned t2 = __shfl_down_sync(0xffffffffu, suf, o);
                if (lane + o < 32) suf += t2;
            }
            unsigned run = suf - tot;
            #pragma unroll
            for (int j = 7; j >= 0; --j) {
                run += hist[lane * 8 + j];
                sscan[lane * 8 + j] = run;
            }
        }
        __syncthreads();

        const unsigned remk = s_remk;
        if (tid < 256) {
            const unsigned ge = sscan[tid];
            const unsigned gt = (tid == 255) ? 0u : sscan[tid + 1];
            if (ge >= remk && gt < remk) { s_t = (unsigned)tid; s_gt = gt; }
        }
        __syncthreads();

        const unsigned t = s_t;
        if (active) {
            if (byt > t)      { selected = true; active = false; }
            else if (byt < t) { active = false; }
        }
        if (tid == 0) s_remk = remk - s_gt;
        __syncthreads();
    }

    // ties at the K-th value: lowest indices win (jax.lax.top_k tie-break)
    {
        const unsigned m_act = __ballot_sync(0xffffffffu, active);
        if (lane == 0) s_wcnt[warp] = __popc(m_act);
        __syncthreads();
        if (tid == 0) {
            int run = 0;
            #pragma unroll
            for (int i = 0; i < 16; i++) { int c = s_wcnt[i]; s_wcnt[i] = run; run += c; }
        }
        __syncthreads();
        if (active) {
            const int irank = s_wcnt[warp] + __popc(m_act & ((1u << lane) - 1u));
            if ((unsigned)irank < s_remk) selected = true;
        }
        __syncthreads();
    }

    // deterministic compaction
    const unsigned m_sel = __ballot_sync(0xffffffffu, selected);
    if (lane == 0) s_wcnt[warp] = __popc(m_sel);
    __syncthreads();
    if (tid == 0) {
        int run = 0;
        #pragma unroll
        for (int i = 0; i < 16; i++) { int c = s_wcnt[i]; s_wcnt[i] = run; run += c; }
    }
    __syncthreads();
    if (selected) {
        const int slot = s_wcnt[warp] + __popc(m_sel & ((1u << lane) - 1u));
        g_sel[b * KK + slot] = make_int2(tid, __float_as_int(tanhf(s * s_inv)));
    }
}

// ---------------- Kernel 3: gather (4 blocks/graph, 64 rows each, 256 thr) ----------------
__global__ __launch_bounds__(256)
void gather_kernel(const float* __restrict__ x)
{
    __shared__ int2 s_sel[64];

    const int tid = threadIdx.x;
    const int b   = blockIdx.x >> 2;
    const int c   = blockIdx.x & 3;

    if (tid < 64) s_sel[tid] = g_sel[b * KK + c * 64 + tid];
    __syncthreads();

    const float* xb = x + (size_t)b * NN * DD + tid;
    float a0 = 0.f, a1 = 0.f, a2 = 0.f, a3 = 0.f;
    #pragma unroll 16
    for (int k = 0; k < 64; k += 4) {
        const int2 p0 = s_sel[k];
        const int2 p1 = s_sel[k + 1];
        const int2 p2 = s_sel[k + 2];
        const int2 p3 = s_sel[k + 3];
        a0 += xb[(size_t)p0.x * DD] * __int_as_float(p0.y);
        a1 += xb[(size_t)p1.x * DD] * __int_as_float(p1.y);
        a2 += xb[(size_t)p2.x * DD] * __int_as_float(p2.y);
        a3 += xb[(size_t)p3.x * DD] * __int_as_float(p3.y);
    }
    g_part[blockIdx.x * DD + tid] = (a0 + a1) + (a2 + a3);
}

// ---------------- Kernel 4: reduce partials ----------------
__global__ __launch_bounds__(256)
void reduce_kernel(float* __restrict__ out)
{
    const int b = blockIdx.x;
    const int t = threadIdx.x;
    const float* p = g_part + b * 4 * DD;
    out[b * DD + t] = (p[t] + p[DD + t] + p[2 * DD + t] + p[3 * DD + t])
                      * (1.0f / (float)KK);
}

extern "C" void kernel_launch(void* const* d_in, const int* in_sizes, int n_in,
                              void* d_out, int out_size)
{
    (void)in_sizes; (void)n_in; (void)out_size;
    const float* x = (const float*)d_in[0];
    const float* w = (const float*)d_in[1];
    float* out = (float*)d_out;

    score_kernel<<<(BB * NN) / 16, 256>>>(x, w);
    rank_kernel<<<BB, 512>>>(w);
    gather_kernel<<<BB * 4, 256>>>(x);
    reduce_kernel<<<BB, 256>>>(out);
}